// round 14
// baseline (speedup 1.0000x reference)
#include <cuda_runtime.h>
#include <cuda_fp16.h>
#include <mma.h>
#include <cstdint>

using namespace nvcuda;

// ---------------- problem constants ----------------
#define BATCH   8
#define NT      8192
#define NS      2048
#define NTOT    (BATCH * NT)      // 65536 target rows
#define C_TGT   128
#define C_SRC   256
#define C_IN    384
#define C_HID   256
#define C_OUT   128

// ---------------- device scratch (no allocs allowed) ----------------
__device__ __align__(128) int    g_knn_idx[NTOT * 3];
__device__ __align__(128) float  g_knn_w  [NTOT * 3];
__device__ __align__(128) __half g_interp_h[NTOT * C_SRC];   // 32 MB
__device__ __align__(128) __half g_hidden_h[NTOT * C_HID];   // 32 MB
__device__ __align__(128) __half g_xt_h   [NTOT * C_TGT];    // 16 MB
__device__ __align__(128) __half g_W1_h   [C_IN * C_HID];
__device__ __align__(128) __half g_Wcat_h [(C_HID + C_IN) * C_OUT];  // [W2;Ws] 640x128
__device__ __align__(128) float  g_bcat   [C_OUT];                   // b2+bs

// ============================================================
// cp.async helpers
// ============================================================
__device__ __forceinline__ void cp16h(__half* dst_smem, const __half* src_gmem) {
    uint32_t d = (uint32_t)__cvta_generic_to_shared(dst_smem);
    asm volatile("cp.async.cg.shared.global [%0], [%1], 16;\n" :: "r"(d), "l"(src_gmem));
}
__device__ __forceinline__ void cp_commit() {
    asm volatile("cp.async.commit_group;\n");
}
template<int N>
__device__ __forceinline__ void cp_wait() {
    asm volatile("cp.async.wait_group %0;\n" :: "n"(N));
}

// ============================================================
// Convert kernels (coalesced, tiny)
// ============================================================
__global__ __launch_bounds__(256)
void cvt_xt_kernel(const float* __restrict__ xt)
{
    const int i4 = blockIdx.x * 256 + threadIdx.x;     // float4 index
    float4 v = ((const float4*)xt)[i4];
    __half2* p = (__half2*)&g_xt_h[i4 * 4];
    p[0] = __floats2half2_rn(v.x, v.y);
    p[1] = __floats2half2_rn(v.z, v.w);
}

__global__ __launch_bounds__(256)
void cvt_weights_kernel(const float* __restrict__ W1,
                        const float* __restrict__ W2,
                        const float* __restrict__ Ws,
                        const float* __restrict__ b2,
                        const float* __restrict__ bs)
{
    const int i = blockIdx.x * 256 + threadIdx.x;
    if (i < C_IN * C_HID)   g_W1_h[i] = __float2half_rn(W1[i]);
    if (i < C_HID * C_OUT)  g_Wcat_h[i] = __float2half_rn(W2[i]);
    if (i < C_IN * C_OUT)   g_Wcat_h[C_HID * C_OUT + i] = __float2half_rn(Ws[i]);
    if (i < C_OUT)          g_bcat[i] = b2[i] + bs[i];
}

// ============================================================
// Kernel 1: 3-NN, split-2 — two threads per target, merged via shfl.
// ============================================================
__global__ __launch_bounds__(256)
void knn_kernel(const float* __restrict__ pos_t, const float* __restrict__ pos_s)
{
    __shared__ float4 sp[NS];             // 32 KB
    const int b    = blockIdx.x >> 6;
    const int tile = blockIdx.x & 63;

    const float* ps = pos_s + (size_t)b * NS * 3;
    for (int s = threadIdx.x; s < NS; s += 256)
        sp[s] = make_float4(ps[3*s], ps[3*s+1], ps[3*s+2], 0.f);
    __syncthreads();

    const int tl   = threadIdx.x >> 1;
    const int half = threadIdx.x & 1;
    const int t = (b * 64 + tile) * 128 + tl;
    const float tx = pos_t[3*t], ty = pos_t[3*t+1], tz = pos_t[3*t+2];

    const int sbeg = half * (NS / 2);
    float d0 = 1e30f, d1 = 1e30f, d2 = 1e30f;
    int   i0 = sbeg,  i1 = sbeg,  i2 = sbeg;

    #pragma unroll 4
    for (int s = sbeg; s < sbeg + NS/2; ++s) {
        float4 p = sp[s];
        float dx = tx - p.x, dy = ty - p.y, dz = tz - p.z;
        float d  = fmaf(dz, dz, fmaf(dy, dy, dx * dx));
        if (d < d2) {
            if (d < d1) {
                d2 = d1; i2 = i1;
                if (d < d0) { d1 = d0; i1 = i0; d0 = d; i0 = s; }
                else        { d1 = d;  i1 = s; }
            } else { d2 = d; i2 = s; }
        }
    }

    const unsigned m = 0xffffffffu;
    float e0 = __shfl_xor_sync(m, d0, 1);
    float e1 = __shfl_xor_sync(m, d1, 1);
    float e2 = __shfl_xor_sync(m, d2, 1);
    int   j0 = __shfl_xor_sync(m, i0, 1);
    int   j1 = __shfl_xor_sync(m, i1, 1);
    int   j2 = __shfl_xor_sync(m, i2, 1);

    if (half == 0) {
        auto ins = [&](float d, int s) {
            if (d < d2) {
                if (d < d1) {
                    d2 = d1; i2 = i1;
                    if (d < d0) { d1 = d0; i1 = i0; d0 = d; i0 = s; }
                    else        { d1 = d;  i1 = s; }
                } else { d2 = d; i2 = s; }
            }
        };
        ins(e0, j0); ins(e1, j1); ins(e2, j2);

        const float w0 = 1.f / fmaxf(d0, 1e-16f);
        const float w1 = 1.f / fmaxf(d1, 1e-16f);
        const float w2 = 1.f / fmaxf(d2, 1e-16f);
        const float inv = 1.f / (w0 + w1 + w2);

        g_knn_w[3*t+0] = w0 * inv;
        g_knn_w[3*t+1] = w1 * inv;
        g_knn_w[3*t+2] = w2 * inv;
        g_knn_idx[3*t+0] = b * NS + i0;
        g_knn_idx[3*t+1] = b * NS + i1;
        g_knn_idx[3*t+2] = b * NS + i2;
    }
}

// ============================================================
// Kernel 2: interpolation gather -> half output.
// ============================================================
__global__ __launch_bounds__(256)
void interp_kernel(const float* __restrict__ xs)
{
    const int row  = blockIdx.x * 8 + (threadIdx.x >> 5);
    const int lane = threadIdx.x & 31;

    const int   i0 = g_knn_idx[3*row+0];
    const int   i1 = g_knn_idx[3*row+1];
    const int   i2 = g_knn_idx[3*row+2];
    const float w0 = g_knn_w[3*row+0];
    const float w1 = g_knn_w[3*row+1];
    const float w2 = g_knn_w[3*row+2];

    const float4* s0 = (const float4*)(xs + (size_t)i0 * C_SRC);
    const float4* s1 = (const float4*)(xs + (size_t)i1 * C_SRC);
    const float4* s2 = (const float4*)(xs + (size_t)i2 * C_SRC);
    __half2* dst = (__half2*)&g_interp_h[(size_t)row * C_SRC];

    #pragma unroll
    for (int h = 0; h < 2; ++h) {
        const int c = lane + h * 32;          // float4 index, 64/row
        float4 a = s0[c], b = s1[c], d = s2[c];
        float rx = w0*a.x + w1*b.x + w2*d.x;
        float ry = w0*a.y + w1*b.y + w2*d.y;
        float rz = w0*a.z + w1*b.z + w2*d.z;
        float rw = w0*a.w + w1*b.w + w2*d.w;
        dst[c*2+0] = __floats2half2_rn(rx, ry);
        dst[c*2+1] = __floats2half2_rn(rz, rw);
    }
}

// ============================================================
// half GEMM: 128x128 tile, 8 warps (4x2), KC=32, cp.async 4-stage.
// ============================================================
#define KC      32
#define PIPE    4
#define SA_LD   40                      // halves/row (32 + 8 pad)
#define SB_LD   136                     // halves/row (128 + 8 pad)
#define SA_HSZ  (128 * SA_LD)           // 5120
#define SB_HSZ  (KC * SB_LD)            // 4352
#define STG_H   (SA_HSZ + SB_HSZ)       // 9472 halves / stage
#define SMEM_BYTES (PIPE * STG_H * 2)   // 75776 B

using FragA = wmma::fragment<wmma::matrix_a, 16, 16, 16, __half, wmma::row_major>;
using FragB = wmma::fragment<wmma::matrix_b, 16, 16, 16, __half, wmma::row_major>;
using FragC = wmma::fragment<wmma::accumulator, 16, 16, 16, float>;

// stage A(128xKC) + B(KCx128) half tiles via cp.async
__device__ __forceinline__ void stage_tiles(
    __half* sA, __half* sB, int tid, int m0,
    const __half* __restrict__ abase, int astride, int aoff,
    const __half* __restrict__ bbase, int bstride, int boff, int n0)
{
    #pragma unroll
    for (int tI = 0; tI < 2; ++tI) {
        const int i = tid + tI * 256;          // 512 chunks of 8 halves
        const int r  = i >> 2;                 // 0..127
        const int c8 = (i & 3) << 3;           // 0,8,16,24
        cp16h(&sA[r * SA_LD + c8], abase + (size_t)(m0 + r) * astride + aoff + c8);
    }
    #pragma unroll
    for (int tI = 0; tI < 2; ++tI) {
        const int i = tid + tI * 256;
        const int r  = i >> 4;                 // 0..31
        const int c8 = (i & 15) << 3;          // 0..120
        cp16h(&sB[r * SB_LD + c8], bbase + (size_t)(boff + r) * bstride + n0 + c8);
    }
}

// consume one KC=32 chunk: 2 x (6 frag loads + 8 mma) per warp
__device__ __forceinline__ void compute_chunk(
    const __half* sA, const __half* sB, int warp_m, int warp_n, FragC fc[2][4])
{
    #pragma unroll
    for (int k16 = 0; k16 < KC; k16 += 16) {
        FragA fa[2];
        FragB fb[4];
        #pragma unroll
        for (int i = 0; i < 2; ++i)
            wmma::load_matrix_sync(fa[i], &sA[(warp_m*32 + i*16) * SA_LD + k16], SA_LD);
        #pragma unroll
        for (int j = 0; j < 4; ++j)
            wmma::load_matrix_sync(fb[j], &sB[k16 * SB_LD + warp_n*64 + j*16], SB_LD);
        #pragma unroll
        for (int i = 0; i < 2; ++i)
            #pragma unroll
            for (int j = 0; j < 4; ++j)
                wmma::mma_sync(fc[i][j], fa[i], fb[j], fc[i][j]);
    }
}

// ------------------------------------------------------------
// GEMM1: hidden = relu([xt | interp] @ W1 + b1)  K=384, N=256 -> half
// ------------------------------------------------------------
__global__ __launch_bounds__(256, 2)
void gemm1_kernel(const float* __restrict__ b1)
{
    extern __shared__ __align__(16) __half sh[];
    const int m0 = blockIdx.x * 128;
    const int n0 = blockIdx.y * 128;
    const int tid = threadIdx.x;
    const int w   = tid >> 5;
    const int warp_m = w & 3;
    const int warp_n = w >> 2;
    const int lane = tid & 31;

    FragC fc[2][4];
    #pragma unroll
    for (int i = 0; i < 2; ++i)
        #pragma unroll
        for (int j = 0; j < 4; ++j)
            wmma::fill_fragment(fc[i][j], 0.f);

    auto stage_it = [&](int it) {
        const int kc = it * KC;
        const __half* ab; int as, ao;
        if (kc < C_TGT) { ab = g_xt_h;     as = C_TGT; ao = kc;         }
        else            { ab = g_interp_h; as = C_SRC; ao = kc - C_TGT; }
        __half* st = sh + (it % PIPE) * STG_H;
        stage_tiles(st, st + SA_HSZ, tid, m0, ab, as, ao, g_W1_h, C_HID, kc, n0);
        cp_commit();
    };

    const int NITER = C_IN / KC;   // 12
    stage_it(0);
    stage_it(1);
    stage_it(2);

    for (int it = 0; it < NITER; ++it) {
        cp_wait<2>();
        __syncthreads();
        if (it + 3 < NITER) stage_it(it + 3);
        else cp_commit();          // keep group count in step
        const __half* st = sh + (it % PIPE) * STG_H;
        compute_chunk(st, st + SA_HSZ, warp_m, warp_n, fc);
    }
    __syncthreads();

    // epilogue: bias + relu -> half hidden
    float* wb = (float*)sh + w * 1024;
    const int gm_base = m0 + warp_m * 32;
    const int gn_base = n0 + warp_n * 64;
    #pragma unroll
    for (int i = 0; i < 2; ++i) {
        #pragma unroll
        for (int j = 0; j < 4; ++j)
            wmma::store_matrix_sync(wb + j*16, fc[i][j], 64, wmma::mem_row_major);
        __syncwarp();
        #pragma unroll
        for (int e = lane; e < 256; e += 32) {
            const int rr = e >> 4;
            const int cc = (e & 15) << 2;
            float4 v = *(float4*)(wb + rr*64 + cc);
            const int gn = gn_base + cc;
            v.x = fmaxf(v.x + b1[gn+0], 0.f);
            v.y = fmaxf(v.y + b1[gn+1], 0.f);
            v.z = fmaxf(v.z + b1[gn+2], 0.f);
            v.w = fmaxf(v.w + b1[gn+3], 0.f);
            __half2 h01 = __floats2half2_rn(v.x, v.y);
            __half2 h23 = __floats2half2_rn(v.z, v.w);
            __half2* p = (__half2*)&g_hidden_h[(size_t)(gm_base + i*16 + rr) * C_HID + gn];
            p[0] = h01; p[1] = h23;
        }
        __syncwarp();
    }
}

// ------------------------------------------------------------
// GEMM2: out = relu([hidden | xt | interp] @ Wcat + bcat)  K=640, N=128
// ------------------------------------------------------------
__global__ __launch_bounds__(256, 2)
void gemm2_kernel(float* __restrict__ out)
{
    extern __shared__ __align__(16) __half sh[];
    const int m0 = blockIdx.x * 128;
    const int tid = threadIdx.x;
    const int w   = tid >> 5;
    const int warp_m = w & 3;
    const int warp_n = w >> 2;
    const int lane = tid & 31;

    FragC fc[2][4];
    #pragma unroll
    for (int i = 0; i < 2; ++i)
        #pragma unroll
        for (int j = 0; j < 4; ++j)
            wmma::fill_fragment(fc[i][j], 0.f);

    auto stage_it = [&](int it) {
        const int kc = it * KC;
        const __half* ab; int as, ao;
        if      (kc < 256) { ab = g_hidden_h; as = C_HID; ao = kc;       }
        else if (kc < 384) { ab = g_xt_h;     as = C_TGT; ao = kc - 256; }
        else               { ab = g_interp_h; as = C_SRC; ao = kc - 384; }
        __half* st = sh + (it % PIPE) * STG_H;
        stage_tiles(st, st + SA_HSZ, tid, m0, ab, as, ao, g_Wcat_h, C_OUT, kc, 0);
        cp_commit();
    };

    const int NITER = (C_HID + C_IN) / KC;   // 20
    stage_it(0);
    stage_it(1);
    stage_it(2);

    for (int it = 0; it < NITER; ++it) {
        cp_wait<2>();
        __syncthreads();
        if (it + 3 < NITER) stage_it(it + 3);
        else cp_commit();
        const __half* st = sh + (it % PIPE) * STG_H;
        compute_chunk(st, st + SA_HSZ, warp_m, warp_n, fc);
    }
    __syncthreads();

    // epilogue: bcat + relu -> fp32 out
    float* wb = (float*)sh + w * 1024;
    const int gm_base = m0 + warp_m * 32;
    const int gn_base = warp_n * 64;
    #pragma unroll
    for (int i = 0; i < 2; ++i) {
        #pragma unroll
        for (int j = 0; j < 4; ++j)
            wmma::store_matrix_sync(wb + j*16, fc[i][j], 64, wmma::mem_row_major);
        __syncwarp();
        #pragma unroll
        for (int e = lane; e < 256; e += 32) {
            const int rr = e >> 4;
            const int cc = (e & 15) << 2;
            float4 v = *(float4*)(wb + rr*64 + cc);
            const int gn = gn_base + cc;
            v.x = fmaxf(v.x + g_bcat[gn+0], 0.f);
            v.y = fmaxf(v.y + g_bcat[gn+1], 0.f);
            v.z = fmaxf(v.z + g_bcat[gn+2], 0.f);
            v.w = fmaxf(v.w + g_bcat[gn+3], 0.f);
            *(float4*)(&out[(size_t)(gm_base + i*16 + rr) * C_OUT + gn]) = v;
        }
        __syncwarp();
    }
}

// ============================================================
// Launch.
// ============================================================
extern "C" void kernel_launch(void* const* d_in, const int* in_sizes, int n_in,
                              void* d_out, int out_size)
{
    const float* xt = (const float*)d_in[0];
    const float* pt = (const float*)d_in[1];
    const float* xs = (const float*)d_in[3];
    const float* ps = (const float*)d_in[4];
    const float* W1 = (const float*)d_in[6];
    const float* b1 = (const float*)d_in[7];
    const float* W2 = (const float*)d_in[8];
    const float* b2 = (const float*)d_in[9];
    const float* Ws = (const float*)d_in[10];
    const float* bs = (const float*)d_in[11];
    float* out = (float*)d_out;

    cudaFuncSetAttribute(gemm1_kernel, cudaFuncAttributeMaxDynamicSharedMemorySize, SMEM_BYTES);
    cudaFuncSetAttribute(gemm2_kernel, cudaFuncAttributeMaxDynamicSharedMemorySize, SMEM_BYTES);

    cvt_xt_kernel     <<<NTOT * C_TGT / 4 / 256, 256>>>(xt);
    cvt_weights_kernel<<<(C_IN * C_HID + 255) / 256, 256>>>(W1, W2, Ws, b2, bs);
    knn_kernel        <<<BATCH * (NT / 128), 256>>>(pt, ps);
    interp_kernel     <<<NTOT / 8, 256>>>(xs);
    gemm1_kernel      <<<dim3(NTOT / 128, C_HID / 128), 256, SMEM_BYTES>>>(b1);
    gemm2_kernel      <<<dim3(NTOT / 128, 1), 256, SMEM_BYTES>>>(out);
}

// round 15
// speedup vs baseline: 1.0373x; 1.0373x over previous
#include <cuda_runtime.h>
#include <cuda_fp16.h>
#include <cstdint>

// ---------------- problem constants ----------------
#define BATCH   8
#define NT      8192
#define NS      2048
#define NTOT    (BATCH * NT)      // 65536 target rows
#define C_TGT   128
#define C_SRC   256
#define C_IN    384
#define C_HID   256
#define C_OUT   128

// ---------------- device scratch (no allocs allowed) ----------------
__device__ __align__(128) int    g_knn_idx[NTOT * 3];
__device__ __align__(128) float  g_knn_w  [NTOT * 3];
__device__ __align__(128) __half g_interp_h[NTOT * C_SRC];   // 32 MB
__device__ __align__(128) __half g_hidden_h[NTOT * C_HID];   // 32 MB
__device__ __align__(128) __half g_xt_h   [NTOT * C_TGT];    // 16 MB
__device__ __align__(128) __half g_W1_h   [C_IN * C_HID];
__device__ __align__(128) __half g_Wcat_h [(C_HID + C_IN) * C_OUT];  // [W2;Ws]
__device__ __align__(128) float  g_bcat   [C_OUT];                   // b2+bs

// ============================================================
// low-level helpers
// ============================================================
__device__ __forceinline__ uint32_t smem_u32(const void* p) {
    return (uint32_t)__cvta_generic_to_shared(p);
}
__device__ __forceinline__ void cp16h(__half* dst_smem, const __half* src_gmem) {
    uint32_t d = smem_u32(dst_smem);
    asm volatile("cp.async.cg.shared.global [%0], [%1], 16;\n" :: "r"(d), "l"(src_gmem));
}
__device__ __forceinline__ void cp_commit() { asm volatile("cp.async.commit_group;\n"); }
template<int N>
__device__ __forceinline__ void cp_wait()   { asm volatile("cp.async.wait_group %0;\n" :: "n"(N)); }

__device__ __forceinline__ void ldsm_x4(uint32_t r[4], uint32_t addr) {
    asm volatile("ldmatrix.sync.aligned.m8n8.x4.shared.b16 {%0,%1,%2,%3}, [%4];"
        : "=r"(r[0]), "=r"(r[1]), "=r"(r[2]), "=r"(r[3]) : "r"(addr));
}
__device__ __forceinline__ void ldsm_x4t(uint32_t r[4], uint32_t addr) {
    asm volatile("ldmatrix.sync.aligned.m8n8.x4.trans.shared.b16 {%0,%1,%2,%3}, [%4];"
        : "=r"(r[0]), "=r"(r[1]), "=r"(r[2]), "=r"(r[3]) : "r"(addr));
}
__device__ __forceinline__ void mma16816(float d[4], const uint32_t a[4],
                                         uint32_t b0, uint32_t b1) {
    asm volatile(
        "mma.sync.aligned.m16n8k16.row.col.f32.f16.f16.f32 "
        "{%0,%1,%2,%3}, {%4,%5,%6,%7}, {%8,%9}, {%0,%1,%2,%3};"
        : "+f"(d[0]), "+f"(d[1]), "+f"(d[2]), "+f"(d[3])
        : "r"(a[0]), "r"(a[1]), "r"(a[2]), "r"(a[3]), "r"(b0), "r"(b1));
}

// ============================================================
// Convert kernels (coalesced, tiny)
// ============================================================
__global__ __launch_bounds__(256)
void cvt_xt_kernel(const float* __restrict__ xt)
{
    const int i4 = blockIdx.x * 256 + threadIdx.x;
    float4 v = ((const float4*)xt)[i4];
    __half2* p = (__half2*)&g_xt_h[i4 * 4];
    p[0] = __floats2half2_rn(v.x, v.y);
    p[1] = __floats2half2_rn(v.z, v.w);
}

__global__ __launch_bounds__(256)
void cvt_weights_kernel(const float* __restrict__ W1,
                        const float* __restrict__ W2,
                        const float* __restrict__ Ws,
                        const float* __restrict__ b2,
                        const float* __restrict__ bs)
{
    const int i = blockIdx.x * 256 + threadIdx.x;
    if (i < C_IN * C_HID)   g_W1_h[i] = __float2half_rn(W1[i]);
    if (i < C_HID * C_OUT)  g_Wcat_h[i] = __float2half_rn(W2[i]);
    if (i < C_IN * C_OUT)   g_Wcat_h[C_HID * C_OUT + i] = __float2half_rn(Ws[i]);
    if (i < C_OUT)          g_bcat[i] = b2[i] + bs[i];
}

// ============================================================
// Kernel 1: 3-NN, split-2 per target (proven).
// ============================================================
__global__ __launch_bounds__(256)
void knn_kernel(const float* __restrict__ pos_t, const float* __restrict__ pos_s)
{
    __shared__ float4 sp[NS];
    const int b    = blockIdx.x >> 6;
    const int tile = blockIdx.x & 63;

    const float* ps = pos_s + (size_t)b * NS * 3;
    for (int s = threadIdx.x; s < NS; s += 256)
        sp[s] = make_float4(ps[3*s], ps[3*s+1], ps[3*s+2], 0.f);
    __syncthreads();

    const int tl   = threadIdx.x >> 1;
    const int half = threadIdx.x & 1;
    const int t = (b * 64 + tile) * 128 + tl;
    const float tx = pos_t[3*t], ty = pos_t[3*t+1], tz = pos_t[3*t+2];

    const int sbeg = half * (NS / 2);
    float d0 = 1e30f, d1 = 1e30f, d2 = 1e30f;
    int   i0 = sbeg,  i1 = sbeg,  i2 = sbeg;

    #pragma unroll 4
    for (int s = sbeg; s < sbeg + NS/2; ++s) {
        float4 p = sp[s];
        float dx = tx - p.x, dy = ty - p.y, dz = tz - p.z;
        float d  = fmaf(dz, dz, fmaf(dy, dy, dx * dx));
        if (d < d2) {
            if (d < d1) {
                d2 = d1; i2 = i1;
                if (d < d0) { d1 = d0; i1 = i0; d0 = d; i0 = s; }
                else        { d1 = d;  i1 = s; }
            } else { d2 = d; i2 = s; }
        }
    }

    const unsigned m = 0xffffffffu;
    float e0 = __shfl_xor_sync(m, d0, 1);
    float e1 = __shfl_xor_sync(m, d1, 1);
    float e2 = __shfl_xor_sync(m, d2, 1);
    int   j0 = __shfl_xor_sync(m, i0, 1);
    int   j1 = __shfl_xor_sync(m, i1, 1);
    int   j2 = __shfl_xor_sync(m, i2, 1);

    if (half == 0) {
        auto ins = [&](float d, int s) {
            if (d < d2) {
                if (d < d1) {
                    d2 = d1; i2 = i1;
                    if (d < d0) { d1 = d0; i1 = i0; d0 = d; i0 = s; }
                    else        { d1 = d;  i1 = s; }
                } else { d2 = d; i2 = s; }
            }
        };
        ins(e0, j0); ins(e1, j1); ins(e2, j2);

        const float w0 = 1.f / fmaxf(d0, 1e-16f);
        const float w1 = 1.f / fmaxf(d1, 1e-16f);
        const float w2 = 1.f / fmaxf(d2, 1e-16f);
        const float inv = 1.f / (w0 + w1 + w2);

        g_knn_w[3*t+0] = w0 * inv;
        g_knn_w[3*t+1] = w1 * inv;
        g_knn_w[3*t+2] = w2 * inv;
        g_knn_idx[3*t+0] = b * NS + i0;
        g_knn_idx[3*t+1] = b * NS + i1;
        g_knn_idx[3*t+2] = b * NS + i2;
    }
}

// ============================================================
// Kernel 2: interpolation gather -> half (proven).
// ============================================================
__global__ __launch_bounds__(256)
void interp_kernel(const float* __restrict__ xs)
{
    const int row  = blockIdx.x * 8 + (threadIdx.x >> 5);
    const int lane = threadIdx.x & 31;

    const int   i0 = g_knn_idx[3*row+0];
    const int   i1 = g_knn_idx[3*row+1];
    const int   i2 = g_knn_idx[3*row+2];
    const float w0 = g_knn_w[3*row+0];
    const float w1 = g_knn_w[3*row+1];
    const float w2 = g_knn_w[3*row+2];

    const float4* s0 = (const float4*)(xs + (size_t)i0 * C_SRC);
    const float4* s1 = (const float4*)(xs + (size_t)i1 * C_SRC);
    const float4* s2 = (const float4*)(xs + (size_t)i2 * C_SRC);
    __half2* dst = (__half2*)&g_interp_h[(size_t)row * C_SRC];

    #pragma unroll
    for (int h = 0; h < 2; ++h) {
        const int c = lane + h * 32;
        float4 a = s0[c], b = s1[c], d = s2[c];
        float rx = w0*a.x + w1*b.x + w2*d.x;
        float ry = w0*a.y + w1*b.y + w2*d.y;
        float rz = w0*a.z + w1*b.z + w2*d.z;
        float rw = w0*a.w + w1*b.w + w2*d.w;
        dst[c*2+0] = __floats2half2_rn(rx, ry);
        dst[c*2+1] = __floats2half2_rn(rz, rw);
    }
}

// ============================================================
// raw-mma GEMM: 128x128 tile, 8 warps (4x2, warp tile 32x64),
// KC=64 (4 k16 steps), 3-stage cp.async, register k-pipelining.
// ============================================================
#define KC      64
#define PIPE    3
#define SA_LD   72                       // halves/row (64 + 8 pad)
#define SB_LD   136                      // halves/row (128 + 8 pad)
#define SA_HSZ  (128 * SA_LD)            // 9216 halves
#define SB_HSZ  (KC * SB_LD)             // 8704 halves
#define STG_H   (SA_HSZ + SB_HSZ)        // 17920 halves
#define STG_B   (STG_H * 2)              // 35840 bytes
#define SMEM_BYTES (PIPE * STG_B)        // 107520 bytes

// stage A(128x64) + B(64x128) half tiles via cp.async
__device__ __forceinline__ void stage_tiles(
    __half* sA, __half* sB, int tid, int m0,
    const __half* __restrict__ abase, int astride, int aoff,
    const __half* __restrict__ bbase, int bstride, int boff, int n0)
{
    #pragma unroll
    for (int tI = 0; tI < 4; ++tI) {
        const int i = tid + tI * 256;          // 1024 chunks of 8 halves (A)
        const int r  = i >> 3;                 // 0..127
        const int c8 = (i & 7) << 3;           // 0..56
        cp16h(&sA[r * SA_LD + c8], abase + (size_t)(m0 + r) * astride + aoff + c8);
    }
    #pragma unroll
    for (int tI = 0; tI < 4; ++tI) {
        const int i = tid + tI * 256;          // 1024 chunks (B)
        const int r  = i >> 4;                 // 0..63
        const int c8 = (i & 15) << 3;          // 0..120
        cp16h(&sB[r * SB_LD + c8], bbase + (size_t)(boff + r) * bstride + n0 + c8);
    }
}

// per-warp compute of one KC=64 chunk with 1-step register double buffer.
// fc: [mi(2)][nj(8)][4] accumulators.
__device__ __forceinline__ void compute_chunk64(
    uint32_t stage_base,        // smem addr of A tile
    uint32_t aLaneOff,          // per-lane A offset (bytes), incl. wm
    uint32_t bLaneOff,          // per-lane B offset (bytes) within B tile, incl. wn
    float fc[2][8][4])
{
    const uint32_t aB = stage_base + aLaneOff;
    const uint32_t bB = stage_base + SA_HSZ * 2 + bLaneOff;

    uint32_t a[2][2][4];
    uint32_t b[2][4][4];

    #pragma unroll
    for (int mi = 0; mi < 2; ++mi)
        ldsm_x4(a[0][mi], aB + mi * (16 * SA_LD * 2));
    #pragma unroll
    for (int nt = 0; nt < 4; ++nt)
        ldsm_x4t(b[0][nt], bB + nt * 32);

    #pragma unroll
    for (int s = 0; s < 4; ++s) {
        const int cur = s & 1, nxt = cur ^ 1;
        if (s < 3) {
            #pragma unroll
            for (int mi = 0; mi < 2; ++mi)
                ldsm_x4(a[nxt][mi], aB + mi * (16 * SA_LD * 2) + (s + 1) * 32);
            #pragma unroll
            for (int nt = 0; nt < 4; ++nt)
                ldsm_x4t(b[nxt][nt], bB + nt * 32 + (s + 1) * (16 * SB_LD * 2));
        }
        #pragma unroll
        for (int mi = 0; mi < 2; ++mi)
            #pragma unroll
            for (int nt = 0; nt < 4; ++nt) {
                mma16816(fc[mi][nt*2+0], a[cur][mi], b[cur][nt][0], b[cur][nt][1]);
                mma16816(fc[mi][nt*2+1], a[cur][mi], b[cur][nt][2], b[cur][nt][3]);
            }
    }
}

// ------------------------------------------------------------
// GEMM1: hidden = relu([xt | interp] @ W1 + b1)  K=384, N=256 -> half
// ------------------------------------------------------------
__global__ __launch_bounds__(256, 2)
void gemm1_kernel(const float* __restrict__ b1)
{
    extern __shared__ __align__(16) __half sh[];
    const int m0 = blockIdx.x * 128;
    const int n0 = blockIdx.y * 128;
    const int tid = threadIdx.x;
    const int w   = tid >> 5;
    const int wm  = w & 3;
    const int wn  = w >> 2;
    const int lane = tid & 31;

    const uint32_t sb = smem_u32(sh);
    const uint32_t aLaneOff = ((wm*32 + (lane & 15)) * SA_LD + (lane >> 4) * 8) * 2;
    const uint32_t bLaneOff = ((lane & 15) * SB_LD + wn*64 + (lane >> 4) * 8) * 2;

    float fc[2][8][4];
    #pragma unroll
    for (int i = 0; i < 2; ++i)
        #pragma unroll
        for (int j = 0; j < 8; ++j)
            #pragma unroll
            for (int q = 0; q < 4; ++q) fc[i][j][q] = 0.f;

    auto stage_it = [&](int it) {
        const int kc = it * KC;
        const __half* ab; int as, ao;
        if (kc < C_TGT) { ab = g_xt_h;     as = C_TGT; ao = kc;         }
        else            { ab = g_interp_h; as = C_SRC; ao = kc - C_TGT; }
        __half* st = sh + (it % PIPE) * STG_H;
        stage_tiles(st, st + SA_HSZ, tid, m0, ab, as, ao, g_W1_h, C_HID, kc, n0);
        cp_commit();
    };

    const int NITER = C_IN / KC;   // 6
    stage_it(0);
    stage_it(1);

    for (int it = 0; it < NITER; ++it) {
        cp_wait<1>();
        __syncthreads();
        if (it + 2 < NITER) stage_it(it + 2);
        compute_chunk64(sb + (it % PIPE) * STG_B, aLaneOff, bLaneOff, fc);
    }

    // epilogue: bias + relu -> half hidden (direct stores)
    const int r0 = m0 + wm*32 + (lane >> 2);
    #pragma unroll
    for (int mi = 0; mi < 2; ++mi) {
        const int ra = r0 + mi*16, rb = ra + 8;
        #pragma unroll
        for (int nj = 0; nj < 8; ++nj) {
            const int col = n0 + wn*64 + nj*8 + (lane & 3)*2;
            float2 bb = *(const float2*)&b1[col];
            float* d = fc[mi][nj];
            __half2 h0 = __floats2half2_rn(fmaxf(d[0]+bb.x, 0.f), fmaxf(d[1]+bb.y, 0.f));
            __half2 h1 = __floats2half2_rn(fmaxf(d[2]+bb.x, 0.f), fmaxf(d[3]+bb.y, 0.f));
            *(__half2*)&g_hidden_h[(size_t)ra * C_HID + col] = h0;
            *(__half2*)&g_hidden_h[(size_t)rb * C_HID + col] = h1;
        }
    }
}

// ------------------------------------------------------------
// GEMM2: out = relu([hidden | xt | interp] @ Wcat + bcat)  K=640, N=128
// ------------------------------------------------------------
__global__ __launch_bounds__(256, 2)
void gemm2_kernel(float* __restrict__ out)
{
    extern __shared__ __align__(16) __half sh[];
    const int m0 = blockIdx.x * 128;
    const int tid = threadIdx.x;
    const int w   = tid >> 5;
    const int wm  = w & 3;
    const int wn  = w >> 2;
    const int lane = tid & 31;

    const uint32_t sb = smem_u32(sh);
    const uint32_t aLaneOff = ((wm*32 + (lane & 15)) * SA_LD + (lane >> 4) * 8) * 2;
    const uint32_t bLaneOff = ((lane & 15) * SB_LD + wn*64 + (lane >> 4) * 8) * 2;

    float fc[2][8][4];
    #pragma unroll
    for (int i = 0; i < 2; ++i)
        #pragma unroll
        for (int j = 0; j < 8; ++j)
            #pragma unroll
            for (int q = 0; q < 4; ++q) fc[i][j][q] = 0.f;

    auto stage_it = [&](int it) {
        const int kc = it * KC;
        const __half* ab; int as, ao;
        if      (kc < 256) { ab = g_hidden_h; as = C_HID; ao = kc;       }
        else if (kc < 384) { ab = g_xt_h;     as = C_TGT; ao = kc - 256; }
        else               { ab = g_interp_h; as = C_SRC; ao = kc - 384; }
        __half* st = sh + (it % PIPE) * STG_H;
        stage_tiles(st, st + SA_HSZ, tid, m0, ab, as, ao, g_Wcat_h, C_OUT, kc, 0);
        cp_commit();
    };

    const int NITER = (C_HID + C_IN) / KC;   // 10
    stage_it(0);
    stage_it(1);

    for (int it = 0; it < NITER; ++it) {
        cp_wait<1>();
        __syncthreads();
        if (it + 2 < NITER) stage_it(it + 2);
        compute_chunk64(sb + (it % PIPE) * STG_B, aLaneOff, bLaneOff, fc);
    }

    // epilogue: bcat + relu -> fp32 out (direct float2 stores)
    const int r0 = m0 + wm*32 + (lane >> 2);
    #pragma unroll
    for (int mi = 0; mi < 2; ++mi) {
        const int ra = r0 + mi*16, rb = ra + 8;
        #pragma unroll
        for (int nj = 0; nj < 8; ++nj) {
            const int col = wn*64 + nj*8 + (lane & 3)*2;
            float2 bb = *(const float2*)&g_bcat[col];
            float* d = fc[mi][nj];
            float2 v0 = make_float2(fmaxf(d[0]+bb.x, 0.f), fmaxf(d[1]+bb.y, 0.f));
            float2 v1 = make_float2(fmaxf(d[2]+bb.x, 0.f), fmaxf(d[3]+bb.y, 0.f));
            *(float2*)&out[(size_t)ra * C_OUT + col] = v0;
            *(float2*)&out[(size_t)rb * C_OUT + col] = v1;
        }
    }
}

// ============================================================
// Launch.
// ============================================================
extern "C" void kernel_launch(void* const* d_in, const int* in_sizes, int n_in,
                              void* d_out, int out_size)
{
    const float* xt = (const float*)d_in[0];
    const float* pt = (const float*)d_in[1];
    const float* xs = (const float*)d_in[3];
    const float* ps = (const float*)d_in[4];
    const float* W1 = (const float*)d_in[6];
    const float* b1 = (const float*)d_in[7];
    const float* W2 = (const float*)d_in[8];
    const float* b2 = (const float*)d_in[9];
    const float* Ws = (const float*)d_in[10];
    const float* bs = (const float*)d_in[11];
    float* out = (float*)d_out;

    cudaFuncSetAttribute(gemm1_kernel, cudaFuncAttributeMaxDynamicSharedMemorySize, SMEM_BYTES);
    cudaFuncSetAttribute(gemm2_kernel, cudaFuncAttributeMaxDynamicSharedMemorySize, SMEM_BYTES);

    cvt_xt_kernel     <<<NTOT * C_TGT / 4 / 256, 256>>>(xt);
    cvt_weights_kernel<<<(C_IN * C_HID + 255) / 256, 256>>>(W1, W2, Ws, b2, bs);
    knn_kernel        <<<BATCH * (NT / 128), 256>>>(pt, ps);
    interp_kernel     <<<NTOT / 8, 256>>>(xs);
    gemm1_kernel      <<<dim3(NTOT / 128, C_HID / 128), 256, SMEM_BYTES>>>(b1);
    gemm2_kernel      <<<dim3(NTOT / 128, 1), 256, SMEM_BYTES>>>(out);
}

// round 16
// speedup vs baseline: 1.0493x; 1.0116x over previous
#include <cuda_runtime.h>
#include <cuda_fp16.h>
#include <cstdint>

// ---------------- problem constants ----------------
#define BATCH   8
#define NT      8192
#define NS      2048
#define NTOT    (BATCH * NT)      // 65536 target rows
#define C_TGT   128
#define C_SRC   256
#define C_IN    384
#define C_HID   256
#define C_OUT   128

// ---------------- device scratch (no allocs allowed) ----------------
__device__ __align__(128) int    g_knn_idx[NTOT * 3];
__device__ __align__(128) float  g_knn_w  [NTOT * 3];
__device__ __align__(128) __half g_interp_h[NTOT * C_SRC];   // 32 MB
__device__ __align__(128) __half g_hidden_h[NTOT * C_HID];   // 32 MB
__device__ __align__(128) __half g_xt_h   [NTOT * C_TGT];    // 16 MB
__device__ __align__(128) __half g_W1_h   [C_IN * C_HID];
__device__ __align__(128) __half g_Wcat_h [(C_HID + C_IN) * C_OUT];  // [W2;Ws]
__device__ __align__(128) float  g_bcat   [C_OUT];                   // b2+bs

// ============================================================
// low-level helpers
// ============================================================
__device__ __forceinline__ uint32_t smem_u32(const void* p) {
    return (uint32_t)__cvta_generic_to_shared(p);
}
__device__ __forceinline__ void cp16h(__half* dst_smem, const __half* src_gmem) {
    uint32_t d = smem_u32(dst_smem);
    asm volatile("cp.async.cg.shared.global [%0], [%1], 16;\n" :: "r"(d), "l"(src_gmem));
}
__device__ __forceinline__ void cp_commit() { asm volatile("cp.async.commit_group;\n"); }
template<int N>
__device__ __forceinline__ void cp_wait()   { asm volatile("cp.async.wait_group %0;\n" :: "n"(N)); }

__device__ __forceinline__ void ldsm_x4(uint32_t r[4], uint32_t addr) {
    asm volatile("ldmatrix.sync.aligned.m8n8.x4.shared.b16 {%0,%1,%2,%3}, [%4];"
        : "=r"(r[0]), "=r"(r[1]), "=r"(r[2]), "=r"(r[3]) : "r"(addr));
}
__device__ __forceinline__ void ldsm_x4t(uint32_t r[4], uint32_t addr) {
    asm volatile("ldmatrix.sync.aligned.m8n8.x4.trans.shared.b16 {%0,%1,%2,%3}, [%4];"
        : "=r"(r[0]), "=r"(r[1]), "=r"(r[2]), "=r"(r[3]) : "r"(addr));
}
__device__ __forceinline__ void mma16816(float d[4], const uint32_t a[4],
                                         uint32_t b0, uint32_t b1) {
    asm volatile(
        "mma.sync.aligned.m16n8k16.row.col.f32.f16.f16.f32 "
        "{%0,%1,%2,%3}, {%4,%5,%6,%7}, {%8,%9}, {%0,%1,%2,%3};"
        : "+f"(d[0]), "+f"(d[1]), "+f"(d[2]), "+f"(d[3])
        : "r"(a[0]), "r"(a[1]), "r"(a[2]), "r"(a[3]), "r"(b0), "r"(b1));
}

// per-warp compute of one KC=64 chunk (4 k16 steps) with 1-step register
// double buffer. SBLD = B smem row pitch in halves.
template<int SBLD>
__device__ __forceinline__ void compute_chunk64(
    uint32_t aBase, uint32_t bBase, float fc[2][8][4])
{
    uint32_t a[2][2][4];
    uint32_t b[2][4][4];

    #pragma unroll
    for (int mi = 0; mi < 2; ++mi)
        ldsm_x4(a[0][mi], aBase + mi * (16 * 72 * 2));
    #pragma unroll
    for (int nt = 0; nt < 4; ++nt)
        ldsm_x4t(b[0][nt], bBase + nt * 32);

    #pragma unroll
    for (int s = 0; s < 4; ++s) {
        const int cur = s & 1, nxt = cur ^ 1;
        if (s < 3) {
            #pragma unroll
            for (int mi = 0; mi < 2; ++mi)
                ldsm_x4(a[nxt][mi], aBase + mi * (16 * 72 * 2) + (s + 1) * 32);
            #pragma unroll
            for (int nt = 0; nt < 4; ++nt)
                ldsm_x4t(b[nxt][nt], bBase + nt * 32 + (s + 1) * (16 * SBLD * 2));
        }
        #pragma unroll
        for (int mi = 0; mi < 2; ++mi)
            #pragma unroll
            for (int nt = 0; nt < 4; ++nt) {
                mma16816(fc[mi][nt*2+0], a[cur][mi], b[cur][nt][0], b[cur][nt][1]);
                mma16816(fc[mi][nt*2+1], a[cur][mi], b[cur][nt][2], b[cur][nt][3]);
            }
    }
}

// ============================================================
// Kernel 1: 3-NN (split-2) + fused weight conversion.
// ============================================================
__global__ __launch_bounds__(256)
void knn_kernel(const float* __restrict__ pos_t, const float* __restrict__ pos_s,
                const float* __restrict__ W1, const float* __restrict__ W2,
                const float* __restrict__ Ws, const float* __restrict__ b2,
                const float* __restrict__ bs)
{
    // --- fused weight cvt (blocks 0..383 only; ~1 elem/thread) ---
    const int gi = blockIdx.x * 256 + threadIdx.x;
    if (gi < C_IN * C_HID)   g_W1_h[gi] = __float2half_rn(W1[gi]);
    if (gi < C_HID * C_OUT)  g_Wcat_h[gi] = __float2half_rn(W2[gi]);
    if (gi < C_IN * C_OUT)   g_Wcat_h[C_HID * C_OUT + gi] = __float2half_rn(Ws[gi]);
    if (gi < C_OUT)          g_bcat[gi] = b2[gi] + bs[gi];

    __shared__ float4 sp[NS];
    const int b    = blockIdx.x >> 6;
    const int tile = blockIdx.x & 63;

    const float* ps = pos_s + (size_t)b * NS * 3;
    for (int s = threadIdx.x; s < NS; s += 256)
        sp[s] = make_float4(ps[3*s], ps[3*s+1], ps[3*s+2], 0.f);
    __syncthreads();

    const int tl   = threadIdx.x >> 1;
    const int half = threadIdx.x & 1;
    const int t = (b * 64 + tile) * 128 + tl;
    const float tx = pos_t[3*t], ty = pos_t[3*t+1], tz = pos_t[3*t+2];

    const int sbeg = half * (NS / 2);
    float d0 = 1e30f, d1 = 1e30f, d2 = 1e30f;
    int   i0 = sbeg,  i1 = sbeg,  i2 = sbeg;

    #pragma unroll 4
    for (int s = sbeg; s < sbeg + NS/2; ++s) {
        float4 p = sp[s];
        float dx = tx - p.x, dy = ty - p.y, dz = tz - p.z;
        float d  = fmaf(dz, dz, fmaf(dy, dy, dx * dx));
        if (d < d2) {
            if (d < d1) {
                d2 = d1; i2 = i1;
                if (d < d0) { d1 = d0; i1 = i0; d0 = d; i0 = s; }
                else        { d1 = d;  i1 = s; }
            } else { d2 = d; i2 = s; }
        }
    }

    const unsigned m = 0xffffffffu;
    float e0 = __shfl_xor_sync(m, d0, 1);
    float e1 = __shfl_xor_sync(m, d1, 1);
    float e2 = __shfl_xor_sync(m, d2, 1);
    int   j0 = __shfl_xor_sync(m, i0, 1);
    int   j1 = __shfl_xor_sync(m, i1, 1);
    int   j2 = __shfl_xor_sync(m, i2, 1);

    if (half == 0) {
        auto ins = [&](float d, int s) {
            if (d < d2) {
                if (d < d1) {
                    d2 = d1; i2 = i1;
                    if (d < d0) { d1 = d0; i1 = i0; d0 = d; i0 = s; }
                    else        { d1 = d;  i1 = s; }
                } else { d2 = d; i2 = s; }
            }
        };
        ins(e0, j0); ins(e1, j1); ins(e2, j2);

        const float w0 = 1.f / fmaxf(d0, 1e-16f);
        const float w1 = 1.f / fmaxf(d1, 1e-16f);
        const float w2 = 1.f / fmaxf(d2, 1e-16f);
        const float inv = 1.f / (w0 + w1 + w2);

        g_knn_w[3*t+0] = w0 * inv;
        g_knn_w[3*t+1] = w1 * inv;
        g_knn_w[3*t+2] = w2 * inv;
        g_knn_idx[3*t+0] = b * NS + i0;
        g_knn_idx[3*t+1] = b * NS + i1;
        g_knn_idx[3*t+2] = b * NS + i2;
    }
}

// ============================================================
// Kernel 2: interpolation gather -> half, + fused xt conversion.
// ============================================================
__global__ __launch_bounds__(256)
void interp_kernel(const float* __restrict__ xs, const float* __restrict__ xt)
{
    // --- fused xt cvt: exactly one float4 per thread ---
    {
        const int i4 = blockIdx.x * 256 + threadIdx.x;   // 2,097,152 total
        float4 v = ((const float4*)xt)[i4];
        __half2* p = (__half2*)&g_xt_h[i4 * 4];
        p[0] = __floats2half2_rn(v.x, v.y);
        p[1] = __floats2half2_rn(v.z, v.w);
    }

    const int row  = blockIdx.x * 8 + (threadIdx.x >> 5);
    const int lane = threadIdx.x & 31;

    const int   i0 = g_knn_idx[3*row+0];
    const int   i1 = g_knn_idx[3*row+1];
    const int   i2 = g_knn_idx[3*row+2];
    const float w0 = g_knn_w[3*row+0];
    const float w1 = g_knn_w[3*row+1];
    const float w2 = g_knn_w[3*row+2];

    const float4* s0 = (const float4*)(xs + (size_t)i0 * C_SRC);
    const float4* s1 = (const float4*)(xs + (size_t)i1 * C_SRC);
    const float4* s2 = (const float4*)(xs + (size_t)i2 * C_SRC);
    __half2* dst = (__half2*)&g_interp_h[(size_t)row * C_SRC];

    #pragma unroll
    for (int h = 0; h < 2; ++h) {
        const int c = lane + h * 32;
        float4 a = s0[c], b = s1[c], d = s2[c];
        float rx = w0*a.x + w1*b.x + w2*d.x;
        float ry = w0*a.y + w1*b.y + w2*d.y;
        float rz = w0*a.z + w1*b.z + w2*d.z;
        float rw = w0*a.w + w1*b.w + w2*d.w;
        dst[c*2+0] = __floats2half2_rn(rx, ry);
        dst[c*2+1] = __floats2half2_rn(rz, rw);
    }
}

// ============================================================
// GEMM1: 128x256 block tile (full N), 512 threads (16 warps, 4x4),
// warp tile 32x64, KC=64, 3-stage cp.async. A staged ONCE per chunk.
// ============================================================
#define SA_LD   72                        // halves/row (64 + 8 pad)
#define SA_HSZ  (128 * SA_LD)             // 9216 halves
#define SB1_LD  264                       // 256 + 8 pad
#define SB1_HSZ (64 * SB1_LD)             // 16896 halves
#define STG1_H  (SA_HSZ + SB1_HSZ)        // 26112 halves
#define STG1_B  (STG1_H * 2)              // 52224 bytes
#define G1_SMEM (3 * STG1_B)              // 156672 bytes

__global__ __launch_bounds__(512, 1)
void gemm1_kernel(const float* __restrict__ b1)
{
    extern __shared__ __align__(16) __half sh[];
    const int m0 = blockIdx.x * 128;
    const int tid = threadIdx.x;
    const int w   = tid >> 5;
    const int wm  = w & 3;       // 4 x 32-row groups
    const int wn  = w >> 2;      // 4 x 64-col groups (N=256)
    const int lane = tid & 31;

    const uint32_t sb = smem_u32(sh);
    const uint32_t aLaneOff = ((wm*32 + (lane & 15)) * SA_LD + (lane >> 4) * 8) * 2;
    const uint32_t bLaneOff = ((lane & 15) * SB1_LD + wn*64 + (lane >> 4) * 8) * 2;

    float fc[2][8][4];
    #pragma unroll
    for (int i = 0; i < 2; ++i)
        #pragma unroll
        for (int j = 0; j < 8; ++j)
            #pragma unroll
            for (int q = 0; q < 4; ++q) fc[i][j][q] = 0.f;

    auto stage_it = [&](int it) {
        const int kc = it * 64;
        const __half* ab; int as, ao;
        if (kc < C_TGT) { ab = g_xt_h;     as = C_TGT; ao = kc;         }
        else            { ab = g_interp_h; as = C_SRC; ao = kc - C_TGT; }
        __half* sA = sh + (it % 3) * STG1_H;
        __half* sB = sA + SA_HSZ;
        #pragma unroll
        for (int t = 0; t < 2; ++t) {                 // A: 1024 x 16B
            const int i = tid + t * 512;
            const int r  = i >> 3;
            const int c8 = (i & 7) << 3;
            cp16h(&sA[r * SA_LD + c8], ab + (size_t)(m0 + r) * as + ao + c8);
        }
        #pragma unroll
        for (int t = 0; t < 4; ++t) {                 // B: 2048 x 16B
            const int i = tid + t * 512;
            const int r  = i >> 5;
            const int c8 = (i & 31) << 3;
            cp16h(&sB[r * SB1_LD + c8], g_W1_h + (size_t)(kc + r) * C_HID + c8);
        }
        cp_commit();
    };

    const int NITER = C_IN / 64;   // 6
    stage_it(0);
    stage_it(1);

    for (int it = 0; it < NITER; ++it) {
        cp_wait<1>();
        __syncthreads();
        if (it + 2 < NITER) stage_it(it + 2);
        const uint32_t stg = sb + (it % 3) * STG1_B;
        compute_chunk64<SB1_LD>(stg + aLaneOff, stg + SA_HSZ * 2 + bLaneOff, fc);
    }

    // epilogue: bias + relu -> half hidden (direct stores)
    const int r0 = m0 + wm*32 + (lane >> 2);
    #pragma unroll
    for (int mi = 0; mi < 2; ++mi) {
        const int ra = r0 + mi*16, rb = ra + 8;
        #pragma unroll
        for (int nj = 0; nj < 8; ++nj) {
            const int col = wn*64 + nj*8 + (lane & 3)*2;
            float2 bb = *(const float2*)&b1[col];
            float* d = fc[mi][nj];
            __half2 h0 = __floats2half2_rn(fmaxf(d[0]+bb.x, 0.f), fmaxf(d[1]+bb.y, 0.f));
            __half2 h1 = __floats2half2_rn(fmaxf(d[2]+bb.x, 0.f), fmaxf(d[3]+bb.y, 0.f));
            *(__half2*)&g_hidden_h[(size_t)ra * C_HID + col] = h0;
            *(__half2*)&g_hidden_h[(size_t)rb * C_HID + col] = h1;
        }
    }
}

// ============================================================
// GEMM2: 128x128 tile, 8 warps (4x2), KC=64, 3-stage (unchanged).
// ============================================================
#define SB2_LD  136
#define SB2_HSZ (64 * SB2_LD)             // 8704 halves
#define STG2_H  (SA_HSZ + SB2_HSZ)        // 17920 halves
#define STG2_B  (STG2_H * 2)              // 35840 bytes
#define G2_SMEM (3 * STG2_B)              // 107520 bytes

__global__ __launch_bounds__(256, 2)
void gemm2_kernel(float* __restrict__ out)
{
    extern __shared__ __align__(16) __half sh[];
    const int m0 = blockIdx.x * 128;
    const int tid = threadIdx.x;
    const int w   = tid >> 5;
    const int wm  = w & 3;
    const int wn  = w >> 2;
    const int lane = tid & 31;

    const uint32_t sb = smem_u32(sh);
    const uint32_t aLaneOff = ((wm*32 + (lane & 15)) * SA_LD + (lane >> 4) * 8) * 2;
    const uint32_t bLaneOff = ((lane & 15) * SB2_LD + wn*64 + (lane >> 4) * 8) * 2;

    float fc[2][8][4];
    #pragma unroll
    for (int i = 0; i < 2; ++i)
        #pragma unroll
        for (int j = 0; j < 8; ++j)
            #pragma unroll
            for (int q = 0; q < 4; ++q) fc[i][j][q] = 0.f;

    auto stage_it = [&](int it) {
        const int kc = it * 64;
        const __half* ab; int as, ao;
        if      (kc < 256) { ab = g_hidden_h; as = C_HID; ao = kc;       }
        else if (kc < 384) { ab = g_xt_h;     as = C_TGT; ao = kc - 256; }
        else               { ab = g_interp_h; as = C_SRC; ao = kc - 384; }
        __half* sA = sh + (it % 3) * STG2_H;
        __half* sB = sA + SA_HSZ;
        #pragma unroll
        for (int t = 0; t < 4; ++t) {                 // A: 1024 x 16B
            const int i = tid + t * 256;
            const int r  = i >> 3;
            const int c8 = (i & 7) << 3;
            cp16h(&sA[r * SA_LD + c8], ab + (size_t)(m0 + r) * as + ao + c8);
        }
        #pragma unroll
        for (int t = 0; t < 4; ++t) {                 // B: 1024 x 16B
            const int i = tid + t * 256;
            const int r  = i >> 4;
            const int c8 = (i & 15) << 3;
            cp16h(&sB[r * SB2_LD + c8], g_Wcat_h + (size_t)(kc + r) * C_OUT + c8);
        }
        cp_commit();
    };

    const int NITER = (C_HID + C_IN) / 64;   // 10
    stage_it(0);
    stage_it(1);

    for (int it = 0; it < NITER; ++it) {
        cp_wait<1>();
        __syncthreads();
        if (it + 2 < NITER) stage_it(it + 2);
        const uint32_t stg = sb + (it % 3) * STG2_B;
        compute_chunk64<SB2_LD>(stg + aLaneOff, stg + SA_HSZ * 2 + bLaneOff, fc);
    }

    // epilogue: bcat + relu -> fp32 out
    const int r0 = m0 + wm*32 + (lane >> 2);
    #pragma unroll
    for (int mi = 0; mi < 2; ++mi) {
        const int ra = r0 + mi*16, rb = ra + 8;
        #pragma unroll
        for (int nj = 0; nj < 8; ++nj) {
            const int col = wn*64 + nj*8 + (lane & 3)*2;
            float2 bb = *(const float2*)&g_bcat[col];
            float* d = fc[mi][nj];
            float2 v0 = make_float2(fmaxf(d[0]+bb.x, 0.f), fmaxf(d[1]+bb.y, 0.f));
            float2 v1 = make_float2(fmaxf(d[2]+bb.x, 0.f), fmaxf(d[3]+bb.y, 0.f));
            *(float2*)&out[(size_t)ra * C_OUT + col] = v0;
            *(float2*)&out[(size_t)rb * C_OUT + col] = v1;
        }
    }
}

// ============================================================
// Launch.
// ============================================================
extern "C" void kernel_launch(void* const* d_in, const int* in_sizes, int n_in,
                              void* d_out, int out_size)
{
    const float* xt = (const float*)d_in[0];
    const float* pt = (const float*)d_in[1];
    const float* xs = (const float*)d_in[3];
    const float* ps = (const float*)d_in[4];
    const float* W1 = (const float*)d_in[6];
    const float* b1 = (const float*)d_in[7];
    const float* W2 = (const float*)d_in[8];
    const float* b2 = (const float*)d_in[9];
    const float* Ws = (const float*)d_in[10];
    const float* bs = (const float*)d_in[11];
    float* out = (float*)d_out;

    cudaFuncSetAttribute(gemm1_kernel, cudaFuncAttributeMaxDynamicSharedMemorySize, G1_SMEM);
    cudaFuncSetAttribute(gemm2_kernel, cudaFuncAttributeMaxDynamicSharedMemorySize, G2_SMEM);

    knn_kernel   <<<BATCH * (NT / 128), 256>>>(pt, ps, W1, W2, Ws, b2, bs);
    interp_kernel<<<NTOT / 8, 256>>>(xs, xt);
    gemm1_kernel <<<NTOT / 128, 512, G1_SMEM>>>(b1);
    gemm2_kernel <<<NTOT / 128, 256, G2_SMEM>>>(out);
}